// round 1
// baseline (speedup 1.0000x reference)
#include <cuda_runtime.h>

#define HW 65536
#define NB 8

// ---------------- scratch (no allocs allowed) ----------------
__device__ float g_t[(size_t)NB * 192 * HW];  // pointwise-conv output, 192 ch
__device__ float g_q[(size_t)NB * 64 * HW];
__device__ float g_k[(size_t)NB * 64 * HW];
__device__ float g_v[(size_t)NB * 64 * HW];

// ---------------- f32x2 helpers ----------------
__device__ __forceinline__ unsigned long long pack2(float lo, float hi) {
    unsigned long long r;
    asm("mov.b64 %0, {%1, %2};" : "=l"(r) : "f"(lo), "f"(hi));
    return r;
}
__device__ __forceinline__ void fma2(unsigned long long& d, unsigned long long a,
                                     unsigned long long b) {
    asm("fma.rn.f32x2 %0, %1, %2, %0;" : "+l"(d) : "l"(a), "l"(b));
}
__device__ __forceinline__ float2 unpack2(unsigned long long v) {
    float2 f;
    asm("mov.b64 {%0, %1}, %2;" : "=f"(f.x), "=f"(f.y) : "l"(v));
    return f;
}

// ================= K1: pointwise convs (GEMM 192x64 @ 64xHW) =================
// block: 128 threads = 16 ocid x 8 pxid, thread tile 12 oc x 8 px, f32x2 over oc pairs
__global__ __launch_bounds__(128) void k1_pointwise(const float* __restrict__ x,
                                                    const float* __restrict__ qw,
                                                    const float* __restrict__ kvw) {
    extern __shared__ float sm[];
    float* Ws = sm;          // [k][oc] 64x192  (48KB)
    float* Xs = sm + 12288;  // [k][px] 64x64   (16KB)
    const int b = blockIdx.y;
    const int px0 = blockIdx.x << 6;
    const int tid = threadIdx.x;

    for (int e = tid; e < 12288; e += 128) {
        int k = e / 192;
        int oc = e - k * 192;
        Ws[e] = (oc < 64) ? __ldg(&qw[oc * 64 + k]) : __ldg(&kvw[(oc - 64) * 64 + k]);
    }
    const float* xb = x + (size_t)b * (64 * HW) + px0;
    for (int e = tid; e < 4096; e += 128) {
        int k = e >> 6, p = e & 63;
        Xs[e] = xb[(size_t)k * HW + p];
    }
    __syncthreads();

    const int ocid = tid >> 3;  // 0..15
    const int pxid = tid & 7;   // 0..7
    unsigned long long acc[48];
#pragma unroll
    for (int i = 0; i < 48; i++) acc[i] = 0ULL;

    const float* xsp = Xs + pxid * 8;
    const float* wsp = Ws + ocid * 12;
#pragma unroll 4
    for (int k = 0; k < 64; k++) {
        float4 xa = *(const float4*)(xsp + k * 64);
        float4 xc = *(const float4*)(xsp + k * 64 + 4);
        unsigned long long xd[8];
        xd[0] = pack2(xa.x, xa.x); xd[1] = pack2(xa.y, xa.y);
        xd[2] = pack2(xa.z, xa.z); xd[3] = pack2(xa.w, xa.w);
        xd[4] = pack2(xc.x, xc.x); xd[5] = pack2(xc.y, xc.y);
        xd[6] = pack2(xc.z, xc.z); xd[7] = pack2(xc.w, xc.w);
        const ulonglong2* wp = (const ulonglong2*)(wsp + k * 192);
        ulonglong2 wA = wp[0];
        ulonglong2 wB = wp[1];
        ulonglong2 wC = wp[2];
        unsigned long long wv[6] = {wA.x, wA.y, wB.x, wB.y, wC.x, wC.y};
#pragma unroll
        for (int i = 0; i < 6; i++)
#pragma unroll
            for (int j = 0; j < 8; j++) fma2(acc[i * 8 + j], xd[j], wv[i]);
    }

    float* outb = g_t + (size_t)b * (192 * HW) + px0 + pxid * 8;
#pragma unroll
    for (int i = 0; i < 6; i++) {
        float r0[8], r1[8];
#pragma unroll
        for (int j = 0; j < 8; j++) {
            float2 u = unpack2(acc[i * 8 + j]);
            r0[j] = u.x;
            r1[j] = u.y;
        }
        int oc0 = ocid * 12 + 2 * i;
        float4* p0 = (float4*)(outb + (size_t)oc0 * HW);
        p0[0] = make_float4(r0[0], r0[1], r0[2], r0[3]);
        p0[1] = make_float4(r0[4], r0[5], r0[6], r0[7]);
        float4* p1 = (float4*)(outb + (size_t)(oc0 + 1) * HW);
        p1[0] = make_float4(r1[0], r1[1], r1[2], r1[3]);
        p1[1] = make_float4(r1[4], r1[5], r1[6], r1[7]);
    }
}

// ================= K2a: depthwise 3x3 on channels 0..63 -> g_q =================
// block 128 = 32 lx x 4 ly, each thread 8 vertical outputs, weights in regs
__global__ __launch_bounds__(128) void k2_dw3(const float* __restrict__ wd) {
    __shared__ float s[34][34];
    const int bz = blockIdx.z;
    const int b = bz >> 6, ch = bz & 63;
    const float* src = g_t + ((size_t)(b * 192 + ch)) * HW;
    float* dst = g_q + ((size_t)(b * 64 + ch)) * HW;
    const int x0 = blockIdx.x << 5, y0 = blockIdx.y << 5;
    const int tid = threadIdx.x;
    for (int e = tid; e < 34 * 34; e += 128) {
        int r = e / 34, cx = e - r * 34;
        int gy = y0 + r - 1, gx = x0 + cx - 1;
        s[r][cx] = ((unsigned)gy < 256u && (unsigned)gx < 256u) ? src[gy * 256 + gx] : 0.f;
    }
    float w9[9];
#pragma unroll
    for (int t = 0; t < 9; t++) w9[t] = __ldg(&wd[ch * 9 + t]);
    __syncthreads();
    const int lx = tid & 31, ly = tid >> 5;
    const int ybase = ly * 8;
    float acc[8];
#pragma unroll
    for (int k = 0; k < 8; k++) acc[k] = 0.f;
#pragma unroll
    for (int ir = 0; ir < 10; ir++) {
        float r3[3];
#pragma unroll
        for (int dx = 0; dx < 3; dx++) r3[dx] = s[ybase + ir][lx + dx];
#pragma unroll
        for (int w = 0; w < 3; w++) {
            int k = ir - w;
            if (k >= 0 && k < 8) {
#pragma unroll
                for (int dx = 0; dx < 3; dx++) acc[k] += w9[w * 3 + dx] * r3[dx];
            }
        }
    }
#pragma unroll
    for (int k = 0; k < 8; k++) dst[(size_t)(y0 + ybase + k) * 256 + x0 + lx] = acc[k];
}

// ================= K2b: depthwise 7x7 on channels 64..191 -> g_k / g_v =================
__global__ __launch_bounds__(128) void k2_dw7(const float* __restrict__ wd) {
    __shared__ float s[38][38];
    const int bz = blockIdx.z;
    const int b = bz >> 7, ch = bz & 127;
    const float* src = g_t + ((size_t)(b * 192 + 64 + ch)) * HW;
    float* dst = (ch < 64) ? g_k + ((size_t)(b * 64 + ch)) * HW
                           : g_v + ((size_t)(b * 64 + ch - 64)) * HW;
    const int x0 = blockIdx.x << 5, y0 = blockIdx.y << 5;
    const int tid = threadIdx.x;
    for (int e = tid; e < 38 * 38; e += 128) {
        int r = e / 38, cx = e - r * 38;
        int gy = y0 + r - 3, gx = x0 + cx - 3;
        s[r][cx] = ((unsigned)gy < 256u && (unsigned)gx < 256u) ? src[gy * 256 + gx] : 0.f;
    }
    float w49[49];
#pragma unroll
    for (int t = 0; t < 49; t++) w49[t] = __ldg(&wd[ch * 49 + t]);
    __syncthreads();
    const int lx = tid & 31, ly = tid >> 5;
    const int ybase = ly * 8;
    float acc[8];
#pragma unroll
    for (int k = 0; k < 8; k++) acc[k] = 0.f;
#pragma unroll
    for (int ir = 0; ir < 14; ir++) {
        float r7[7];
#pragma unroll
        for (int dx = 0; dx < 7; dx++) r7[dx] = s[ybase + ir][lx + dx];
#pragma unroll
        for (int w = 0; w < 7; w++) {
            int k = ir - w;
            if (k >= 0 && k < 8) {
#pragma unroll
                for (int dx = 0; dx < 7; dx++) acc[k] += w49[w * 7 + dx] * r7[dx];
            }
        }
    }
#pragma unroll
    for (int k = 0; k < 8; k++) dst[(size_t)(y0 + ybase + k) * 256 + x0 + lx] = acc[k];
}

// ================= K3: per-patch circular conv + LN + gate + proj =================
__device__ __forceinline__ void conv_row8(const float* __restrict__ qrow,
                                          const float* __restrict__ kbase, int i,
                                          float acc[8]) {
#pragma unroll
    for (int j = 0; j < 8; j++) acc[j] = 0.f;
#pragma unroll
    for (int a = 0; a < 8; a++) {
        const int ia = (i - a) & 7;
        const float* kr = kbase + ia * 20;
        float kk[16];
        float4 t0 = *(const float4*)(kr);
        float4 t1 = *(const float4*)(kr + 4);
        float4 t2 = *(const float4*)(kr + 8);
        float4 t3 = *(const float4*)(kr + 12);
        kk[0] = t0.x; kk[1] = t0.y; kk[2] = t0.z; kk[3] = t0.w;
        kk[4] = t1.x; kk[5] = t1.y; kk[6] = t1.z; kk[7] = t1.w;
        kk[8] = t2.x; kk[9] = t2.y; kk[10] = t2.z; kk[11] = t2.w;
        kk[12] = t3.x; kk[13] = t3.y; kk[14] = t3.z; kk[15] = t3.w;
        float qq[8];
        float4 q0 = *(const float4*)(qrow + a * 8);
        float4 q1 = *(const float4*)(qrow + a * 8 + 4);
        qq[0] = q0.x; qq[1] = q0.y; qq[2] = q0.z; qq[3] = q0.w;
        qq[4] = q1.x; qq[5] = q1.y; qq[6] = q1.z; qq[7] = q1.w;
#pragma unroll
        for (int bb = 0; bb < 8; bb++)
#pragma unroll
            for (int j = 0; j < 8; j++) acc[j] += qq[bb] * kk[8 + j - bb];
    }
}

__global__ __launch_bounds__(256) void k3_attn(const float* __restrict__ lnw,
                                               const float* __restrict__ lnb,
                                               const float* __restrict__ pw,
                                               const float* __restrict__ pb,
                                               float* __restrict__ out) {
    extern __shared__ float sm[];
    float* qs = sm;          // [c][64]; becomes conv output (os) after conv
    float* ks2 = sm + 4096;  // [c][8][20] duplicated k rows; later mu/rs/pws
    const int tid = threadIdx.x;
    const int b = blockIdx.z;
    const size_t pbase = (size_t)blockIdx.y * (8 * 256) + (size_t)blockIdx.x * 8;
    const size_t cb = (size_t)b * 64 * HW + pbase;

    for (int e = tid; e < 4096; e += 256) {
        int c = e >> 6, p = e & 63, i = p >> 3, j = p & 7;
        size_t g = cb + (size_t)c * HW + i * 256 + j;
        qs[e] = g_q[g];
        float kvv = g_k[g];
        ks2[c * 160 + i * 20 + j] = kvv;
        ks2[c * 160 + i * 20 + 8 + j] = kvv;
    }
    __syncthreads();

    float accA[8], accB[8];
    {
        int c = tid >> 3, i = tid & 7;
        conv_row8(qs + c * 64, ks2 + c * 160, i, accA);
        conv_row8(qs + (c + 32) * 64, ks2 + (c + 32) * 160, i, accB);
    }
    __syncthreads();  // all conv reads of qs/ks2 done
    {
        int c = tid >> 3, i = tid & 7;
        float4* d0 = (float4*)(qs + c * 64 + i * 8);
        d0[0] = make_float4(accA[0], accA[1], accA[2], accA[3]);
        d0[1] = make_float4(accA[4], accA[5], accA[6], accA[7]);
        float4* d1 = (float4*)(qs + (c + 32) * 64 + i * 8);
        d1[0] = make_float4(accB[0], accB[1], accB[2], accB[3]);
        d1[1] = make_float4(accB[4], accB[5], accB[6], accB[7]);
    }
    float* mu = ks2;
    float* rs = ks2 + 64;
    float* pws = ks2 + 128;
    for (int e = tid; e < 4096; e += 256) pws[e] = __ldg(&pw[e]);
    __syncthreads();

    if (tid < 64) {
        float s1 = 0.f, s2 = 0.f;
#pragma unroll 8
        for (int c = 0; c < 64; c++) {
            float v = qs[c * 64 + tid];
            s1 += v;
            s2 += v * v;
        }
        float m = s1 * 0.015625f;
        float var = s2 * 0.015625f - m * m;
        mu[tid] = m;
        rs[tid] = rsqrtf(var + 1e-5f);
    }
    __syncthreads();

    for (int e = tid; e < 4096; e += 256) {
        int c = e >> 6, p = e & 63, i = p >> 3, j = p & 7;
        float vv = g_v[cb + (size_t)c * HW + i * 256 + j];
        float o = qs[e];
        o = (o - mu[p]) * rs[p] * __ldg(&lnw[c]) + __ldg(&lnb[c]);
        qs[e] = o * vv;
    }
    __syncthreads();

#pragma unroll
    for (int s = 0; s < 2; s++) {
        int r = tid + (s << 8);
        int co = r >> 3, i = r & 7;
        float acc[8] = {0.f, 0.f, 0.f, 0.f, 0.f, 0.f, 0.f, 0.f};
        const float* osr = qs + i * 8;
        const float* pwr = pws + co * 64;
#pragma unroll 4
        for (int c = 0; c < 64; c++) {
            float wvv = pwr[c];
            float4 o0 = *(const float4*)(osr + c * 64);
            float4 o1 = *(const float4*)(osr + c * 64 + 4);
            acc[0] += wvv * o0.x; acc[1] += wvv * o0.y;
            acc[2] += wvv * o0.z; acc[3] += wvv * o0.w;
            acc[4] += wvv * o1.x; acc[5] += wvv * o1.y;
            acc[6] += wvv * o1.z; acc[7] += wvv * o1.w;
        }
        float bias = __ldg(&pb[co]);
        float4* op = (float4*)(out + cb + (size_t)co * HW + (size_t)i * 256);
        op[0] = make_float4(acc[0] + bias, acc[1] + bias, acc[2] + bias, acc[3] + bias);
        op[1] = make_float4(acc[4] + bias, acc[5] + bias, acc[6] + bias, acc[7] + bias);
    }
}

// ================= launcher =================
extern "C" void kernel_launch(void* const* d_in, const int* in_sizes, int n_in,
                              void* d_out, int out_size) {
    (void)in_sizes;
    (void)n_in;
    (void)out_size;
    const float* x = (const float*)d_in[0];
    const float* q_w = (const float*)d_in[1];
    const float* q_dw = (const float*)d_in[2];
    const float* kv_w = (const float*)d_in[3];
    const float* kv_dw = (const float*)d_in[4];
    const float* ln_w = (const float*)d_in[5];
    const float* ln_b = (const float*)d_in[6];
    const float* pj_w = (const float*)d_in[7];
    const float* pj_b = (const float*)d_in[8];
    float* out = (float*)d_out;

    cudaFuncSetAttribute(k1_pointwise, cudaFuncAttributeMaxDynamicSharedMemorySize, 65536);
    cudaFuncSetAttribute(k3_attn, cudaFuncAttributeMaxDynamicSharedMemorySize, 57344);

    k1_pointwise<<<dim3(1024, NB), 128, 65536>>>(x, q_w, kv_w);
    k2_dw3<<<dim3(8, 8, NB * 64), 128>>>(q_dw);
    k2_dw7<<<dim3(8, 8, NB * 128), 128>>>(kv_dw);
    k3_attn<<<dim3(32, 32, NB), 256, 57344>>>(ln_w, ln_b, pj_w, pj_b, out);
}

// round 2
// speedup vs baseline: 1.4527x; 1.4527x over previous
#include <cuda_runtime.h>

#define HW 65536
#define NB 8
typedef unsigned long long ull;

// ---------------- scratch (no allocs allowed) ----------------
__device__ float g_t[(size_t)NB * 192 * HW];  // pointwise-conv output, 192 ch
__device__ float g_q[(size_t)NB * 64 * HW];
__device__ float g_k[(size_t)NB * 64 * HW];
__device__ float g_v[(size_t)NB * 64 * HW];

// ---------------- f32x2 helpers ----------------
__device__ __forceinline__ ull pack2(float lo, float hi) {
    ull r;
    asm("mov.b64 %0, {%1, %2};" : "=l"(r) : "f"(lo), "f"(hi));
    return r;
}
__device__ __forceinline__ void fma2(ull& d, ull a, ull b) {
    asm("fma.rn.f32x2 %0, %1, %2, %0;" : "+l"(d) : "l"(a), "l"(b));
}
__device__ __forceinline__ float2 unpack2(ull v) {
    float2 f;
    asm("mov.b64 {%0, %1}, %2;" : "=f"(f.x), "=f"(f.y) : "l"(v));
    return f;
}

// ================= K1: pointwise convs (GEMM 192x64 @ 64xHW) =================
__global__ __launch_bounds__(128) void k1_pointwise(const float* __restrict__ x,
                                                    const float* __restrict__ qw,
                                                    const float* __restrict__ kvw) {
    extern __shared__ float sm[];
    float* Ws = sm;          // [k][oc] 64x192  (48KB)
    float* Xs = sm + 12288;  // [k][px] 64x64   (16KB)
    const int b = blockIdx.y;
    const int px0 = blockIdx.x << 6;
    const int tid = threadIdx.x;

    for (int e = tid; e < 12288; e += 128) {
        int k = e / 192;
        int oc = e - k * 192;
        Ws[e] = (oc < 64) ? __ldg(&qw[oc * 64 + k]) : __ldg(&kvw[(oc - 64) * 64 + k]);
    }
    const float* xb = x + (size_t)b * (64 * HW) + px0;
    for (int e = tid; e < 4096; e += 128) {
        int k = e >> 6, p = e & 63;
        Xs[e] = xb[(size_t)k * HW + p];
    }
    __syncthreads();

    const int ocid = tid >> 3;  // 0..15
    const int pxid = tid & 7;   // 0..7
    ull acc[48];
#pragma unroll
    for (int i = 0; i < 48; i++) acc[i] = 0ULL;

    const float* xsp = Xs + pxid * 8;
    const float* wsp = Ws + ocid * 12;
#pragma unroll 4
    for (int k = 0; k < 64; k++) {
        float4 xa = *(const float4*)(xsp + k * 64);
        float4 xc = *(const float4*)(xsp + k * 64 + 4);
        ull xd[8];
        xd[0] = pack2(xa.x, xa.x); xd[1] = pack2(xa.y, xa.y);
        xd[2] = pack2(xa.z, xa.z); xd[3] = pack2(xa.w, xa.w);
        xd[4] = pack2(xc.x, xc.x); xd[5] = pack2(xc.y, xc.y);
        xd[6] = pack2(xc.z, xc.z); xd[7] = pack2(xc.w, xc.w);
        const ulonglong2* wp = (const ulonglong2*)(wsp + k * 192);
        ulonglong2 wA = wp[0];
        ulonglong2 wB = wp[1];
        ulonglong2 wC = wp[2];
        ull wv[6] = {wA.x, wA.y, wB.x, wB.y, wC.x, wC.y};
#pragma unroll
        for (int i = 0; i < 6; i++)
#pragma unroll
            for (int j = 0; j < 8; j++) fma2(acc[i * 8 + j], xd[j], wv[i]);
    }

    float* outb = g_t + (size_t)b * (192 * HW) + px0 + pxid * 8;
#pragma unroll
    for (int i = 0; i < 6; i++) {
        float r0[8], r1[8];
#pragma unroll
        for (int j = 0; j < 8; j++) {
            float2 u = unpack2(acc[i * 8 + j]);
            r0[j] = u.x;
            r1[j] = u.y;
        }
        int oc0 = ocid * 12 + 2 * i;
        float4* p0 = (float4*)(outb + (size_t)oc0 * HW);
        p0[0] = make_float4(r0[0], r0[1], r0[2], r0[3]);
        p0[1] = make_float4(r0[4], r0[5], r0[6], r0[7]);
        float4* p1 = (float4*)(outb + (size_t)(oc0 + 1) * HW);
        p1[0] = make_float4(r1[0], r1[1], r1[2], r1[3]);
        p1[1] = make_float4(r1[4], r1[5], r1[6], r1[7]);
    }
}

// ================= K2a: depthwise 3x3, 16 rows/thread =================
// block 128 = 32 lx x 4 ly; tile 32 wide x 64 tall
__global__ __launch_bounds__(128) void k2_dw3(const float* __restrict__ wd) {
    __shared__ float s[66][34];
    const int bz = blockIdx.z;
    const int b = bz >> 6, ch = bz & 63;
    const float* src = g_t + ((size_t)(b * 192 + ch)) * HW;
    float* dst = g_q + ((size_t)(b * 64 + ch)) * HW;
    const int x0 = blockIdx.x << 5, y0 = blockIdx.y << 6;
    const int tid = threadIdx.x;
    for (int e = tid; e < 66 * 34; e += 128) {
        int r = e / 34, cx = e - r * 34;
        int gy = y0 + r - 1, gx = x0 + cx - 1;
        s[r][cx] = ((unsigned)gy < 256u && (unsigned)gx < 256u) ? src[gy * 256 + gx] : 0.f;
    }
    float w9[9];
#pragma unroll
    for (int t = 0; t < 9; t++) w9[t] = __ldg(&wd[ch * 9 + t]);
    __syncthreads();
    const int lx = tid & 31, ly = tid >> 5;
    const int ybase = ly * 16;
    float acc[16];
#pragma unroll
    for (int k = 0; k < 16; k++) acc[k] = 0.f;
#pragma unroll
    for (int ir = 0; ir < 18; ir++) {
        float r3[3];
#pragma unroll
        for (int dx = 0; dx < 3; dx++) r3[dx] = s[ybase + ir][lx + dx];
#pragma unroll
        for (int w = 0; w < 3; w++) {
            int k = ir - w;
            if (k >= 0 && k < 16) {
#pragma unroll
                for (int dx = 0; dx < 3; dx++) acc[k] += w9[w * 3 + dx] * r3[dx];
            }
        }
    }
#pragma unroll
    for (int k = 0; k < 16; k++) dst[(size_t)(y0 + ybase + k) * 256 + x0 + lx] = acc[k];
}

// ================= K2b: depthwise 7x7, 16 rows/thread =================
__global__ __launch_bounds__(128) void k2_dw7(const float* __restrict__ wd) {
    __shared__ float s[70][38];
    const int bz = blockIdx.z;
    const int b = bz >> 7, ch = bz & 127;
    const float* src = g_t + ((size_t)(b * 192 + 64 + ch)) * HW;
    float* dst = (ch < 64) ? g_k + ((size_t)(b * 64 + ch)) * HW
                           : g_v + ((size_t)(b * 64 + ch - 64)) * HW;
    const int x0 = blockIdx.x << 5, y0 = blockIdx.y << 6;
    const int tid = threadIdx.x;
    for (int e = tid; e < 70 * 38; e += 128) {
        int r = e / 38, cx = e - r * 38;
        int gy = y0 + r - 3, gx = x0 + cx - 3;
        s[r][cx] = ((unsigned)gy < 256u && (unsigned)gx < 256u) ? src[gy * 256 + gx] : 0.f;
    }
    float w49[49];
#pragma unroll
    for (int t = 0; t < 49; t++) w49[t] = __ldg(&wd[ch * 49 + t]);
    __syncthreads();
    const int lx = tid & 31, ly = tid >> 5;
    const int ybase = ly * 16;
    float acc[16];
#pragma unroll
    for (int k = 0; k < 16; k++) acc[k] = 0.f;
#pragma unroll
    for (int ir = 0; ir < 22; ir++) {
        float r7[7];
#pragma unroll
        for (int dx = 0; dx < 7; dx++) r7[dx] = s[ybase + ir][lx + dx];
#pragma unroll
        for (int w = 0; w < 7; w++) {
            int k = ir - w;
            if (k >= 0 && k < 16) {
#pragma unroll
                for (int dx = 0; dx < 7; dx++) acc[k] += w49[w * 7 + dx] * r7[dx];
            }
        }
    }
#pragma unroll
    for (int k = 0; k < 16; k++) dst[(size_t)(y0 + ybase + k) * 256 + x0 + lx] = acc[k];
}

// ================= K3: per-patch circular conv + LN + gate + proj =================
// smem: qs[64][68] | kd[64][164] (later: p1/p2 partials at +0, pwt at +512) | mu[64] rs[64]
#define QP 68
#define KP 164
#define K3_SMEM ((64 * QP + 64 * KP + 128) * 4)

__global__ __launch_bounds__(256) void k3_attn(const float* __restrict__ lnw,
                                               const float* __restrict__ lnb,
                                               const float* __restrict__ pw,
                                               const float* __restrict__ pb,
                                               float* __restrict__ out) {
    extern __shared__ float sm[];
    float* qs = sm;                 // [64][QP]
    float* kd = sm + 64 * QP;       // [64][KP]
    float* mu = kd + 64 * KP;       // [64]
    float* rs = mu + 64;            // [64]
    float* p1 = kd;                 // stats partials (after conv)
    float* p2 = kd + 256;
    float* pwt = kd + 512;          // transposed proj weights [c][QP] (after conv)

    const int tid = threadIdx.x;
    const int b = blockIdx.z;
    const size_t cb =
        (size_t)b * 64 * HW + (size_t)blockIdx.y * (8 * 256) + (size_t)blockIdx.x * 8;

    // ---- stage q (pitch QP) and k duplicated (pitch KP, rows of 20) ----
    for (int idx = tid; idx < 1024; idx += 256) {
        int c = idx >> 4, rem = idx & 15, r = rem >> 1, h = rem & 1;
        size_t g = cb + (size_t)c * HW + r * 256 + h * 4;
        float4 qv = *(const float4*)(g_q + g);
        *(float4*)(qs + c * QP + r * 8 + h * 4) = qv;
        float4 kv = *(const float4*)(g_k + g);
        *(float4*)(kd + c * KP + r * 20 + h * 4) = kv;
        *(float4*)(kd + c * KP + r * 20 + 8 + h * 4) = kv;
    }
    __syncthreads();

    // ---- circular conv: thread = (channel, row-pair) ----
    const int c = tid >> 2, ti = tid & 3, i0 = ti * 2;
    float acc0[8], acc1[8];
#pragma unroll
    for (int j = 0; j < 8; j++) { acc0[j] = 0.f; acc1[j] = 0.f; }
    const float* qc = qs + c * QP;
    const float* kc = kd + c * KP;
#pragma unroll
    for (int a = 0; a < 8; a++) {
        float q[8];
        float4 qA = *(const float4*)(qc + a * 8);
        float4 qB = *(const float4*)(qc + a * 8 + 4);
        q[0] = qA.x; q[1] = qA.y; q[2] = qA.z; q[3] = qA.w;
        q[4] = qB.x; q[5] = qB.y; q[6] = qB.z; q[7] = qB.w;
        int r0 = (i0 - a) & 7;
        int r1 = (r0 + 1) & 7;
        float kk0[16], kk1[16];
        {
            const float4* k0 = (const float4*)(kc + r0 * 20);
            float4 t0 = k0[0], t1 = k0[1], t2 = k0[2], t3 = k0[3];
            kk0[0] = t0.x; kk0[1] = t0.y; kk0[2] = t0.z; kk0[3] = t0.w;
            kk0[4] = t1.x; kk0[5] = t1.y; kk0[6] = t1.z; kk0[7] = t1.w;
            kk0[8] = t2.x; kk0[9] = t2.y; kk0[10] = t2.z; kk0[11] = t2.w;
            kk0[12] = t3.x; kk0[13] = t3.y; kk0[14] = t3.z; kk0[15] = t3.w;
        }
        {
            const float4* k1 = (const float4*)(kc + r1 * 20);
            float4 t0 = k1[0], t1 = k1[1], t2 = k1[2], t3 = k1[3];
            kk1[0] = t0.x; kk1[1] = t0.y; kk1[2] = t0.z; kk1[3] = t0.w;
            kk1[4] = t1.x; kk1[5] = t1.y; kk1[6] = t1.z; kk1[7] = t1.w;
            kk1[8] = t2.x; kk1[9] = t2.y; kk1[10] = t2.z; kk1[11] = t2.w;
            kk1[12] = t3.x; kk1[13] = t3.y; kk1[14] = t3.z; kk1[15] = t3.w;
        }
#pragma unroll
        for (int bb = 0; bb < 8; bb++)
#pragma unroll
            for (int j = 0; j < 8; j++) {
                acc0[j] += q[bb] * kk0[8 + j - bb];
                acc1[j] += q[bb] * kk1[8 + j - bb];
            }
    }
    __syncthreads();  // all conv reads of qs/kd done

    // store conv output (overwrite qs)
    *(float4*)(qs + c * QP + i0 * 8) = make_float4(acc0[0], acc0[1], acc0[2], acc0[3]);
    *(float4*)(qs + c * QP + i0 * 8 + 4) = make_float4(acc0[4], acc0[5], acc0[6], acc0[7]);
    *(float4*)(qs + c * QP + (i0 + 1) * 8) = make_float4(acc1[0], acc1[1], acc1[2], acc1[3]);
    *(float4*)(qs + c * QP + (i0 + 1) * 8 + 4) =
        make_float4(acc1[4], acc1[5], acc1[6], acc1[7]);
    __syncthreads();

    // ---- stage transposed proj weights into pwt (kd region now free) ----
    {
        int co = tid >> 2, seg = tid & 3;
        const float* src = pw + co * 64 + seg * 16;
#pragma unroll
        for (int m = 0; m < 4; m++) {
            float4 wv = *(const float4*)(src + m * 4);
            int cb4 = seg * 16 + m * 4;
            pwt[(cb4 + 0) * QP + co] = wv.x;
            pwt[(cb4 + 1) * QP + co] = wv.y;
            pwt[(cb4 + 2) * QP + co] = wv.z;
            pwt[(cb4 + 3) * QP + co] = wv.w;
        }
    }
    // ---- partial LN stats ----
    {
        int pt = tid & 63, grp = tid >> 6;
        float s1 = 0.f, s2 = 0.f;
#pragma unroll
        for (int cc = grp * 16; cc < grp * 16 + 16; cc++) {
            float v = qs[cc * QP + pt];
            s1 += v;
            s2 += v * v;
        }
        p1[grp * 64 + pt] = s1;
        p2[grp * 64 + pt] = s2;
    }
    __syncthreads();
    if (tid < 64) {
        float s1 = p1[tid] + p1[64 + tid] + p1[128 + tid] + p1[192 + tid];
        float s2 = p2[tid] + p2[64 + tid] + p2[128 + tid] + p2[192 + tid];
        float m = s1 * 0.015625f;
        float var = s2 * 0.015625f - m * m;
        mu[tid] = m;
        rs[tid] = rsqrtf(var + 1e-5f);
    }
    __syncthreads();

    // ---- LN + gate by v ----
    for (int idx = tid; idx < 1024; idx += 256) {
        int cc = idx >> 4, rem = idx & 15, r = rem >> 1, h = rem & 1;
        int ps = r * 8 + h * 4;
        float4 vv = *(const float4*)(g_v + cb + (size_t)cc * HW + r * 256 + h * 4);
        float4 o = *(float4*)(qs + cc * QP + ps);
        float lw = __ldg(lnw + cc), lb = __ldg(lnb + cc);
        o.x = ((o.x - mu[ps + 0]) * rs[ps + 0] * lw + lb) * vv.x;
        o.y = ((o.y - mu[ps + 1]) * rs[ps + 1] * lw + lb) * vv.y;
        o.z = ((o.z - mu[ps + 2]) * rs[ps + 2] * lw + lb) * vv.z;
        o.w = ((o.w - mu[ps + 3]) * rs[ps + 3] * lw + lb) * vv.w;
        *(float4*)(qs + cc * QP + ps) = o;
    }
    __syncthreads();

    // ---- proj: 4co x 4px per thread, f32x2 ----
    {
        int pxg = tid & 15, cog = tid >> 4;
        int i = pxg >> 1, j0 = (pxg & 1) * 4;
        ull acc[8];
#pragma unroll
        for (int u = 0; u < 8; u++) acc[u] = 0ULL;
#pragma unroll 4
        for (int cc = 0; cc < 64; cc++) {
            float4 qv = *(const float4*)(qs + cc * QP + pxg * 4);
            ull q01 = pack2(qv.x, qv.y);
            ull q23 = pack2(qv.z, qv.w);
            float4 wv = *(const float4*)(pwt + cc * QP + cog * 4);
            ull w0 = pack2(wv.x, wv.x);
            ull w1 = pack2(wv.y, wv.y);
            ull w2 = pack2(wv.z, wv.z);
            ull w3 = pack2(wv.w, wv.w);
            fma2(acc[0], w0, q01); fma2(acc[1], w0, q23);
            fma2(acc[2], w1, q01); fma2(acc[3], w1, q23);
            fma2(acc[4], w2, q01); fma2(acc[5], w2, q23);
            fma2(acc[6], w3, q01); fma2(acc[7], w3, q23);
        }
#pragma unroll
        for (int u = 0; u < 4; u++) {
            int co = cog * 4 + u;
            float bias = __ldg(pb + co);
            float2 a01 = unpack2(acc[u * 2]);
            float2 a23 = unpack2(acc[u * 2 + 1]);
            *(float4*)(out + cb + (size_t)co * HW + (size_t)i * 256 + j0) =
                make_float4(a01.x + bias, a01.y + bias, a23.x + bias, a23.y + bias);
        }
    }
}

// ================= launcher =================
extern "C" void kernel_launch(void* const* d_in, const int* in_sizes, int n_in,
                              void* d_out, int out_size) {
    (void)in_sizes;
    (void)n_in;
    (void)out_size;
    const float* x = (const float*)d_in[0];
    const float* q_w = (const float*)d_in[1];
    const float* q_dw = (const float*)d_in[2];
    const float* kv_w = (const float*)d_in[3];
    const float* kv_dw = (const float*)d_in[4];
    const float* ln_w = (const float*)d_in[5];
    const float* ln_b = (const float*)d_in[6];
    const float* pj_w = (const float*)d_in[7];
    const float* pj_b = (const float*)d_in[8];
    float* out = (float*)d_out;

    cudaFuncSetAttribute(k1_pointwise, cudaFuncAttributeMaxDynamicSharedMemorySize, 65536);
    cudaFuncSetAttribute(k3_attn, cudaFuncAttributeMaxDynamicSharedMemorySize, K3_SMEM);

    k1_pointwise<<<dim3(1024, NB), 128, 65536>>>(x, q_w, kv_w);
    k2_dw3<<<dim3(8, 4, NB * 64), 128>>>(q_dw);
    k2_dw7<<<dim3(8, 4, NB * 128), 128>>>(kv_dw);
    k3_attn<<<dim3(32, 32, NB), 256, K3_SMEM>>>(ln_w, ln_b, pj_w, pj_b, out);
}